// round 16
// baseline (speedup 1.0000x reference)
#include <cuda_runtime.h>
#include <cooperative_groups.h>
#include <cstdint>
#include <cstddef>

namespace cg = cooperative_groups;

#define BB      64
#define TIN     200
#define TOUT    400
#define DENC    512
#define DRNN    1024
#define PRE     256
#define ATT     128
#define KSZ     31
#define NMEL    80
#define GATESZ  4096
#define KSPLIT  8
#define NB      128
#define NT      256
#define WPAD    36
// smem float offsets
#define OFF_XS    (2 * 256 * WPAD)            // 18432
#define OFF_XIN   (OFF_XS + 32 * 68)          // 20608
#define SMEM_FLOATS (OFF_XIN + 1536)          // 22144
#define SMEM_BYTES  (SMEM_FLOATS * 4)         // 88576

// packed fp32x2 FMA (Blackwell FFMA2) — bit-identical to two scalar FFMAs
#define FMA2(d, a, b) asm("fma.rn.f32x2 %0, %1, %2, %0;" : "+l"(d) : "l"(a), "l"(b))

// ---------------- device scratch ----------------
__device__ float d_xs[(size_t)TOUT * BB * PRE];
__device__ float d_pm[(size_t)BB * TIN * ATT];    // [b][t][a]
__device__ float d_ah[BB * DRNN];
__device__ float d_aca[2][BB * DRNN];             // double-buffered attn cell state
__device__ float d_dh[BB * DRNN];
__device__ float d_dc[BB * DRNN];
__device__ float d_aw[BB * TIN];
__device__ float d_cum[BB * TIN];
__device__ float d_actx[2][BB * DENC];            // double-buffered context
__device__ float d_e[BB * TIN];
__device__ float d_gpart_a[(size_t)KSPLIT * GATESZ * BB];   // [s][b][m]
__device__ float d_gpart_d[(size_t)KSPLIT * GATESZ * BB];   // [s][b][m]

// ---------------- fast math ----------------
__device__ __forceinline__ float tanh_fast(float x) {
    float ax = fabsf(x);
    float t  = __expf(-2.0f * ax);
    float r  = __fdividef(1.0f - t, 1.0f + t);
    return copysignf(r, x);
}
__device__ __forceinline__ float sig_fast(float x) {
    return __fdividef(1.0f, 1.0f + __expf(-x));
}

// ---------------- init (runs every replay: determinism) ----------------
__global__ void init_state_kernel() {
    int i = blockIdx.x * 256 + threadIdx.x;
    int n = gridDim.x * 256;
    for (int k = i; k < BB * DRNN; k += n) {
        d_ah[k]=0.f; d_aca[0][k]=0.f; d_aca[1][k]=0.f; d_dh[k]=0.f; d_dc[k]=0.f;
    }
    for (int k = i; k < BB * TIN;  k += n) { d_aw[k]=0.f; d_cum[k]=0.f; }
    for (int k = i; k < BB * DENC; k += n) { d_actx[0][k]=0.f; d_actx[1][k]=0.f; }
}

// ---------------- prenet (all 400 steps, parallel) ----------------
__global__ void prenet_kernel(const float* __restrict__ dec_in,
                              const float* __restrict__ Wp1,
                              const float* __restrict__ Wp2) {
    __shared__ float di_s[32 * NMEL];
    __shared__ float h1_s[32 * PRE];
    int t = blockIdx.x, b0 = blockIdx.y * 32, tid = threadIdx.x;
    for (int i = tid; i < 32 * NMEL; i += 256) {
        int b = i / NMEL, k = i - b * NMEL;
        di_s[i] = (t == 0) ? 0.f : dec_in[((size_t)(t - 1) * BB + (b0 + b)) * NMEL + k];
    }
    __syncthreads();
    {
        const float* wr = Wp1 + tid * NMEL;
        for (int c = 0; c < 2; c++) {
            float acc[16];
            #pragma unroll
            for (int r = 0; r < 16; r++) acc[r] = 0.f;
            for (int k = 0; k < NMEL; k++) {
                float w = wr[k];
                #pragma unroll
                for (int r = 0; r < 16; r++)
                    acc[r] = fmaf(w, di_s[(c * 16 + r) * NMEL + k], acc[r]);
            }
            #pragma unroll
            for (int r = 0; r < 16; r++)
                h1_s[(c * 16 + r) * PRE + tid] = fmaxf(acc[r], 0.f);
        }
    }
    __syncthreads();
    {
        const float* wr = Wp2 + tid * PRE;
        for (int c = 0; c < 2; c++) {
            float acc[16];
            #pragma unroll
            for (int r = 0; r < 16; r++) acc[r] = 0.f;
            for (int k = 0; k < PRE; k++) {
                float w = wr[k];
                #pragma unroll
                for (int r = 0; r < 16; r++)
                    acc[r] = fmaf(w, h1_s[(c * 16 + r) * PRE + k], acc[r]);
            }
            #pragma unroll
            for (int r = 0; r < 16; r++)
                d_xs[((size_t)t * BB + (b0 + c * 16 + r)) * PRE + tid] = fmaxf(acc[r], 0.f);
        }
    }
}

// ---------------- processed memory: pm[b][t][a] ----------------
__global__ void procmem_kernel(const float* __restrict__ enc,
                               const float* __restrict__ Wmem) {
    __shared__ float es[8 * DENC];
    int b = blockIdx.x, t0 = blockIdx.y * 8, tid = threadIdx.x;  // 128 threads
    for (int i = tid; i < 8 * DENC; i += 128)
        es[i] = enc[((size_t)b * TIN + t0) * DENC + i];
    __syncthreads();
    const float* wr = Wmem + tid * DENC;
    float acc[8];
    #pragma unroll
    for (int r = 0; r < 8; r++) acc[r] = 0.f;
    for (int e = 0; e < DENC; e++) {
        float w = wr[e];
        #pragma unroll
        for (int r = 0; r < 8; r++) acc[r] = fmaf(w, es[r * DENC + e], acc[r]);
    }
    #pragma unroll
    for (int r = 0; r < 8; r++)
        d_pm[((size_t)b * TIN + t0 + r) * ATT + tid] = acc[r];
}

// ---------------- GEMM: 8m x 8b tile; W via cp.async double-buffered smem ---
// gpart[split][b][m] = sum_k W[m][k] * x[b][k]; block tile 256m x 64b, chunk 32k
__device__ __forceinline__ void gemm_phase(
    float* smem,
    const float* __restrict__ Wih, int K1,
    const float* __restrict__ Whh,
    const float* __restrict__ x0, int L0,
    const float* __restrict__ x1,           // DENC-wide context segment
    const float* __restrict__ x2,
    int kstart, int Kq, int item, float* gpart_base) {
    float* Wsm = smem;                 // 2 x 256 x WPAD
    float* Xs  = smem + OFF_XS;        // 32 x 68
    const int tid = threadIdx.x;
    const int m0 = (item & 15) * 256;
    const int nch = Kq >> 5;
    const int tr = tid >> 3, tb = tid & 7;
    const int L01 = L0 + DENC;
    const int kq4 = (tid & 7) * 4;
    const int jcol = tid & 7;          // 16B piece within a 128B W row

    unsigned long long acc2[8][4];
    #pragma unroll
    for (int m = 0; m < 8; m++)
        #pragma unroll
        for (int p = 0; p < 4; p++) acc2[m][p] = 0ull;

    // stage one 256x32 W chunk into smem buffer via cp.async (8x16B per thread)
    auto stage_w = [&](int kc, int buf) {
        const float* wb; int wstr;
        if (kc < K1) { wb = Wih + kc;        wstr = K1;   }
        else         { wb = Whh + (kc - K1); wstr = 1024; }
        unsigned dbase = (unsigned)__cvta_generic_to_shared(Wsm + buf * 256 * WPAD);
        #pragma unroll
        for (int p = 0; p < 8; p++) {
            int r = (tid >> 3) + 32 * p;
            const float* src = wb + (size_t)(m0 + r) * wstr + jcol * 4;
            unsigned dst = dbase + (unsigned)(r * WPAD + jcol * 4) * 4u;
            asm volatile("cp.async.cg.shared.global [%0], [%1], 16;"
                         :: "r"(dst), "l"(src));
        }
        asm volatile("cp.async.commit_group;");
    };

    float4 xreg[2];
    {   // prologue: W chunk 0 (async) + X chunk 0 (registers)
        stage_w(kstart, 0);
        int kc = kstart;
        const float* xb; int xstr, xcol;
        if (kc < L0)       { xb = x0; xstr = L0;   xcol = kc; }
        else if (kc < L01) { xb = x1; xstr = DENC; xcol = kc - L0; }
        else               { xb = x2; xstr = 1024; xcol = kc - L01; }
        xreg[0] = *(const float4*)&xb[(size_t)tr * xstr + xcol + kq4];
        xreg[1] = *(const float4*)&xb[(size_t)(tr + 32) * xstr + xcol + kq4];
    }

    for (int c = 0; c < nch; c++) {
        int kc = kstart + c * 32;
        __syncthreads();   // previous chunk's Xs/Wsm reads complete
        {   // stage X (k-major)
            float v0[4] = {xreg[0].x, xreg[0].y, xreg[0].z, xreg[0].w};
            float v1[4] = {xreg[1].x, xreg[1].y, xreg[1].z, xreg[1].w};
            #pragma unroll
            for (int j = 0; j < 4; j++) {
                Xs[(kq4 + j) * 68 + tr]      = v0[j];
                Xs[(kq4 + j) * 68 + tr + 32] = v1[j];
            }
        }
        if (c + 1 < nch) {   // async-prefetch next W chunk + next X chunk
            stage_w(kc + 32, (c + 1) & 1);
            int kn = kc + 32;
            const float* xb; int xstr, xcol;
            if (kn < L0)       { xb = x0; xstr = L0;   xcol = kn; }
            else if (kn < L01) { xb = x1; xstr = DENC; xcol = kn - L0; }
            else               { xb = x2; xstr = 1024; xcol = kn - L01; }
            xreg[0] = *(const float4*)&xb[(size_t)tr * xstr + xcol + kq4];
            xreg[1] = *(const float4*)&xb[(size_t)(tr + 32) * xstr + xcol + kq4];
            asm volatile("cp.async.wait_group 1;");
        } else {
            asm volatile("cp.async.wait_group 0;");
        }
        __syncthreads();

        const float* wcur = Wsm + (c & 1) * 256 * WPAD + (tr * 8) * WPAD;
        #pragma unroll
        for (int g = 0; g < 8; g++) {
            float4 wr[8];
            #pragma unroll
            for (int i = 0; i < 8; i++)
                wr[i] = *(const float4*)&wcur[i * WPAD + g * 4];
            #pragma unroll
            for (int j = 0; j < 4; j++) {
                int k = g * 4 + j;
                ulonglong2 xa  = *(const ulonglong2*)&Xs[k * 68 + tb * 8];
                ulonglong2 xb2 = *(const ulonglong2*)&Xs[k * 68 + tb * 8 + 4];
                unsigned long long xp0 = xa.x, xp1 = xa.y, xp2 = xb2.x, xp3 = xb2.y;
                #pragma unroll
                for (int m = 0; m < 8; m++) {
                    float wv = ((const float*)&wr[m])[j];
                    unsigned long long w2;
                    unsigned wu = __float_as_uint(wv);
                    asm("mov.b64 %0, {%1, %1};" : "=l"(w2) : "r"(wu));
                    FMA2(acc2[m][0], w2, xp0);
                    FMA2(acc2[m][1], w2, xp1);
                    FMA2(acc2[m][2], w2, xp2);
                    FMA2(acc2[m][3], w2, xp3);
                }
            }
        }
    }

    // write out: gpart[split][b][m]
    float* gp = gpart_base + (size_t)(item >> 4) * (GATESZ * BB);
    #pragma unroll
    for (int p = 0; p < 4; p++) {
        float2 f[8];
        #pragma unroll
        for (int m = 0; m < 8; m++) f[m] = *(float2*)&acc2[m][p];
        int b0 = tb * 8 + 2 * p;
        *(float4*)&gp[(size_t)b0 * GATESZ + m0 + tr * 8] =
            make_float4(f[0].x, f[1].x, f[2].x, f[3].x);
        *(float4*)&gp[(size_t)b0 * GATESZ + m0 + tr * 8 + 4] =
            make_float4(f[4].x, f[5].x, f[6].x, f[7].x);
        *(float4*)&gp[(size_t)(b0 + 1) * GATESZ + m0 + tr * 8] =
            make_float4(f[0].y, f[1].y, f[2].y, f[3].y);
        *(float4*)&gp[(size_t)(b0 + 1) * GATESZ + m0 + tr * 8 + 4] =
            make_float4(f[4].y, f[5].y, f[6].y, f[7].y);
    }
}

// ---------------- per-batch LSTM gates ----------------
__device__ __forceinline__ void gates_batch(const float* __restrict__ bias, int b,
                                            const float* __restrict__ gpart_base,
                                            float* __restrict__ hg,
                                            const float* __restrict__ c_old,
                                            float* __restrict__ c_new,
                                            float* hs, bool write_global) {
    int tid = threadIdx.x;
    #pragma unroll
    for (int r = 0; r < 4; r++) {
        int j = tid + 256 * r;
        float gi = bias[j], gf = bias[j + 1024], gg = bias[j + 2048], go = bias[j + 3072];
        #pragma unroll
        for (int s = 0; s < KSPLIT; s++) {
            const float* gp = gpart_base + (size_t)s * (GATESZ * BB) + (size_t)b * GATESZ;
            gi += gp[j]; gf += gp[j + 1024]; gg += gp[j + 2048]; go += gp[j + 3072];
        }
        float cn = sig_fast(gf) * c_old[b * DRNN + j] + sig_fast(gi) * tanh_fast(gg);
        float hn = sig_fast(go) * tanh_fast(cn);
        if (write_global) { c_new[b * DRNN + j] = cn; hg[b * DRNN + j] = hn; }
        if (hs) hs[j] = hn;
    }
}

// ---------------- dec gates + output projection for step t_prev ----------------
__device__ __forceinline__ void decgates_out(float* xin, const float* __restrict__ b_d,
                                             const float* __restrict__ Wp,
                                             const float* __restrict__ bp,
                                             const float* __restrict__ actx_old,
                                             float* __restrict__ outs, int b, int t_prev) {
    int tid = threadIdx.x;
    gates_batch(b_d, b, d_gpart_d, d_dh, d_dc, d_dc, xin, true);
    for (int i = tid; i < 512; i += 256) xin[1024 + i] = actx_old[b * DENC + i];
    __syncthreads();
    int o = tid >> 1, hf = tid & 1;
    float s0 = 0.f, s1 = 0.f, s2 = 0.f, s3 = 0.f;
    if (o < NMEL) {
        const float4* wr4 = (const float4*)(Wp + (size_t)o * 1536 + hf * 768);
        const float4* xp4 = (const float4*)(xin + hf * 768);
        for (int k = 0; k < 192; k += 4) {
            float4 w0 = wr4[k],     x0 = xp4[k];
            float4 w1 = wr4[k + 1], x1 = xp4[k + 1];
            float4 w2 = wr4[k + 2], x2 = xp4[k + 2];
            float4 w3 = wr4[k + 3], x3 = xp4[k + 3];
            s0 = fmaf(w0.x, x0.x, s0); s0 = fmaf(w0.y, x0.y, s0);
            s0 = fmaf(w0.z, x0.z, s0); s0 = fmaf(w0.w, x0.w, s0);
            s1 = fmaf(w1.x, x1.x, s1); s1 = fmaf(w1.y, x1.y, s1);
            s1 = fmaf(w1.z, x1.z, s1); s1 = fmaf(w1.w, x1.w, s1);
            s2 = fmaf(w2.x, x2.x, s2); s2 = fmaf(w2.y, x2.y, s2);
            s2 = fmaf(w2.z, x2.z, s2); s2 = fmaf(w2.w, x2.w, s2);
            s3 = fmaf(w3.x, x3.x, s3); s3 = fmaf(w3.y, x3.y, s3);
            s3 = fmaf(w3.z, x3.z, s3); s3 = fmaf(w3.w, x3.w, s3);
        }
    }
    float s = (s0 + s1) + (s2 + s3);
    s += __shfl_xor_sync(0xffffffffu, s, 1);
    if (o < NMEL && hf == 0)
        outs[((size_t)b * TOUT + t_prev) * NMEL + o] = s + bp[o];
    __syncthreads();
}

// ---------------- persistent kernel: 3 grid.syncs per step ----------------
// attention pool layout (floats, within dynamic smem base):
//   ah_s[1024]@0 | aw_s[256]@1024 | cum_s[256]@1280 | v_s[128]@1536
//   pq_s[128]@1664 | Wc_s[1984]@1792 | Wloc_s[4096]@3776 | locraw[100*36]@7872
__global__ void __launch_bounds__(NT, 1)
persistent_kernel(const float* __restrict__ enc, const int* __restrict__ lens,
                  const float* __restrict__ Wih_a, const float* __restrict__ Whh_a,
                  const float* __restrict__ b_a,
                  const float* __restrict__ Wq, const float* __restrict__ Wconv,
                  const float* __restrict__ Wloc, const float* __restrict__ v,
                  const float* __restrict__ Wih_d, const float* __restrict__ Whh_d,
                  const float* __restrict__ b_d,
                  const float* __restrict__ Wp, const float* __restrict__ bp,
                  float* __restrict__ outs, float* __restrict__ aligns) {
    cg::grid_group grid = cg::this_grid();
    extern __shared__ __align__(16) float pool[];
    const int bid = blockIdx.x, tid = threadIdx.x;
    const int wid = tid >> 5, lane = tid & 31;
    const int bat = bid >> 1, q = bid & 1;   // attention: 2 blocks per batch
    const int ksp = bid >> 4;                // GEMM K-split index (8)

    // prologue: attn-GEMM(0) — actx(-1) = zeros in d_actx[1]
    gemm_phase(pool, Wih_a, 768, Whh_a,
               d_xs, PRE, d_actx[1], d_ah,
               ksp * 224, 224, bid, d_gpart_a);
    grid.sync();

    for (int t = 0; t < TOUT; t++) {
        float* actx_cur = d_actx[t & 1];          // written by PC2(t)
        float* actx_prev = d_actx[(t + 1) & 1];   // actx(t-1)

        // ======== PC1: gates + pq + conv + energies (2 blocks/batch, 100 pos)
        {
            float* ah_s   = pool;
            float* aw_s   = pool + 1024;
            float* cum_s  = pool + 1280;
            float* v_s    = pool + 1536;
            float* pq_s   = pool + 1664;
            float* Wc_s   = pool + 1792;
            float* Wloc_s = pool + 3776;
            float* locraw = pool + 7872;   // [pos_l*36 + f], 100 pos

            for (int i = tid; i < 4096; i += NT) Wloc_s[i] = Wloc[i];
            for (int i = tid; i < 1984; i += NT) Wc_s[i] = Wconv[i];
            if (tid < 128) v_s[tid] = v[tid];
            for (int i = tid; i < TIN; i += NT) {
                aw_s[i]  = d_aw[bat * TIN + i];
                cum_s[i] = d_cum[bat * TIN + i];
            }
            gates_batch(b_a, bat, d_gpart_a, d_ah,
                        d_aca[t & 1], d_aca[(t + 1) & 1], ah_s, q == 0);
            __syncthreads();

            // pq = Wq @ ah (redundant per block)
            {
                const float4* ah4 = (const float4*)ah_s;
                for (int a = wid * 16; a < wid * 16 + 16; a++) {
                    const float4* wr4 = (const float4*)(Wq + (size_t)a * DRNN);
                    float s = 0.f;
                    for (int k4 = lane; k4 < 256; k4 += 32) {
                        float4 w = wr4[k4]; float4 x = ah4[k4];
                        s = fmaf(w.x, x.x, s); s = fmaf(w.y, x.y, s);
                        s = fmaf(w.z, x.z, s); s = fmaf(w.w, x.w, s);
                    }
                    #pragma unroll
                    for (int o = 16; o > 0; o >>= 1) s += __shfl_xor_sync(0xffffffffu, s, o);
                    if (lane == 0) pq_s[a] = s;
                }
            }
            __syncthreads();

            // conv for this block's 100 positions
            int pos0 = q * 100;
            for (int u = tid; u < 3200; u += NT) {
                int f = u & 31, pos_l = u >> 5;
                int pos = pos0 + pos_l;
                const float* w0 = Wc_s + f * 62;
                float a0 = 0.f;
                #pragma unroll
                for (int kk = 0; kk < KSZ; kk++) {
                    int ip = pos + kk - 15;
                    if (ip >= 0 && ip < TIN)
                        a0 += aw_s[ip] * w0[kk] + cum_s[ip] * w0[31 + kk];
                }
                locraw[pos_l * 36 + f] = a0;
            }
            __syncthreads();

            // energies: thread = (pos_l, a-half); dual lp chains
            int ah = tid & 1, pos_l = tid >> 1;
            int len_b = lens[bat];
            int pos = pos0 + pos_l;
            float part = 0.f;
            if (pos_l < 100 && pos < len_b) {
                float4 lr4[8];
                #pragma unroll
                for (int j = 0; j < 8; j++)
                    lr4[j] = *(const float4*)&locraw[pos_l * 36 + j * 4];
                const float* lr = (const float*)lr4;
                const float4* pm4 = (const float4*)(d_pm + ((size_t)bat * TIN + pos) * ATT + ah * 64);
                const float* vv  = v_s + ah * 64;
                const float* pqp = pq_s + ah * 64;
                const float* wl  = Wloc_s + ah * 64 * 32;
                #pragma unroll 4
                for (int i = 0; i < 16; i++) {
                    float4 pmv = pm4[i];
                    #pragma unroll
                    for (int jp = 0; jp < 2; jp++) {
                        int a0 = i * 4 + jp * 2;
                        float lp0 = pqp[a0], lp1 = pqp[a0 + 1];
                        const float* wl0 = wl + a0 * 32;
                        const float* wl1 = wl0 + 32;
                        #pragma unroll
                        for (int f = 0; f < 32; f++) {
                            lp0 = fmaf(wl0[f], lr[f], lp0);
                            lp1 = fmaf(wl1[f], lr[f], lp1);
                        }
                        float pm0 = ((const float*)&pmv)[jp * 2];
                        float pm1 = ((const float*)&pmv)[jp * 2 + 1];
                        part = fmaf(vv[a0],     tanh_fast(lp0 + pm0), part);
                        part = fmaf(vv[a0 + 1], tanh_fast(lp1 + pm1), part);
                    }
                }
            }
            part += __shfl_xor_sync(0xffffffffu, part, 1);
            if (pos_l < 100 && ah == 0)
                d_e[bat * TIN + pos] = (pos < len_b) ? part : -1.0e8f;
        }
        grid.sync();

        // ======== PC2: softmax + context slice; q==1 blocks add decgates+out(t-1)
        {
            float* e_s  = pool;        // 256
            float* red  = pool + 256;  // 256
            float* aw_s = pool + 512;  // 256
            for (int i = tid; i < TIN; i += NT) e_s[i] = d_e[bat * TIN + i];
            __syncthreads();
            red[tid] = (tid < TIN) ? e_s[tid] : -3.402823466e38f;
            __syncthreads();
            for (int s = 128; s > 0; s >>= 1) {
                if (tid < s) red[tid] = fmaxf(red[tid], red[tid + s]);
                __syncthreads();
            }
            float mx = red[0];
            __syncthreads();
            float p = (tid < TIN) ? __expf(e_s[tid] - mx) : 0.f;
            red[tid] = p;
            __syncthreads();
            for (int s = 128; s > 0; s >>= 1) {
                if (tid < s) red[tid] += red[tid + s];
                __syncthreads();
            }
            float inv = __fdividef(1.0f, red[0]);
            __syncthreads();
            if (tid < TIN) {
                float awn = p * inv;
                aw_s[tid] = awn;
                if (q == 0) {
                    d_aw[bat * TIN + tid]  = awn;
                    d_cum[bat * TIN + tid] = d_cum[bat * TIN + tid] + awn;
                    aligns[((size_t)bat * TOUT + t) * TIN + tid] = awn;
                }
            }
            __syncthreads();
            // context: one column per thread; 8 accumulators for MLP
            const float* ep = enc + (size_t)bat * TIN * DENC + q * 256 + tid;
            float a0=0.f,a1=0.f,a2=0.f,a3=0.f,a4=0.f,a5=0.f,a6=0.f,a7=0.f;
            for (int pz = 0; pz < TIN; pz += 8) {
                a0 = fmaf(aw_s[pz],     ep[(size_t)pz * DENC],       a0);
                a1 = fmaf(aw_s[pz + 1], ep[(size_t)(pz + 1) * DENC], a1);
                a2 = fmaf(aw_s[pz + 2], ep[(size_t)(pz + 2) * DENC], a2);
                a3 = fmaf(aw_s[pz + 3], ep[(size_t)(pz + 3) * DENC], a3);
                a4 = fmaf(aw_s[pz + 4], ep[(size_t)(pz + 4) * DENC], a4);
                a5 = fmaf(aw_s[pz + 5], ep[(size_t)(pz + 5) * DENC], a5);
                a6 = fmaf(aw_s[pz + 6], ep[(size_t)(pz + 6) * DENC], a6);
                a7 = fmaf(aw_s[pz + 7], ep[(size_t)(pz + 7) * DENC], a7);
            }
            actx_cur[bat * DENC + q * 256 + tid] =
                ((a0 + a1) + (a2 + a3)) + ((a4 + a5) + (a6 + a7));
            // dec gates + output projection for step t-1 on q==1 blocks
            if (q == 1 && t > 0)
                decgates_out(pool + OFF_XIN, b_d, Wp, bp, actx_prev, outs, bat, t - 1);
        }
        grid.sync();

        // ======== PG: dec-GEMM(t) + attn-GEMM(t+1), 17 even chunks per block
        gemm_phase(pool, Wih_d, 1536, Whh_d,
                   d_ah, 1024, actx_cur, d_dh,
                   ksp * 320, 320, bid, d_gpart_d);
        if (t + 1 < TOUT)
            gemm_phase(pool, Wih_a, 768, Whh_a,
                       d_xs + (size_t)(t + 1) * BB * PRE, PRE, actx_cur, d_ah,
                       ksp * 224, 224, bid, d_gpart_a);
        grid.sync();
    }

    // epilogue: final dec gates + out(t = TOUT-1) on odd blocks
    if (q == 1) {
        __syncthreads();
        decgates_out(pool + OFF_XIN, b_d, Wp, bp, d_actx[(TOUT - 1) & 1],
                     outs, bat, TOUT - 1);
    }
}

// ---------------- launch ----------------
extern "C" void kernel_launch(void* const* d_in, const int* in_sizes, int n_in,
                              void* d_out, int out_size) {
    const float* enc   = (const float*)d_in[0];
    const float* dec   = (const float*)d_in[1];
    const int*   lens  = (const int*)  d_in[2];
    const float* Wp1   = (const float*)d_in[3];
    const float* Wp2   = (const float*)d_in[4];
    const float* Wih_a = (const float*)d_in[5];
    const float* Whh_a = (const float*)d_in[6];
    const float* b_a   = (const float*)d_in[7];
    const float* Wq    = (const float*)d_in[8];
    const float* Wmem  = (const float*)d_in[9];
    const float* v     = (const float*)d_in[10];
    const float* Wconv = (const float*)d_in[11];
    const float* Wloc  = (const float*)d_in[12];
    const float* Wih_d = (const float*)d_in[13];
    const float* Whh_d = (const float*)d_in[14];
    const float* b_d   = (const float*)d_in[15];
    const float* Wp    = (const float*)d_in[16];
    const float* bp    = (const float*)d_in[17];

    float* outs   = (float*)d_out;
    float* aligns = outs + (size_t)BB * TOUT * NMEL;

    cudaFuncSetAttribute(persistent_kernel,
                         cudaFuncAttributeMaxDynamicSharedMemorySize, SMEM_BYTES);

    init_state_kernel<<<64, 256>>>();
    prenet_kernel<<<dim3(TOUT, 2), 256>>>(dec, Wp1, Wp2);
    procmem_kernel<<<dim3(BB, TIN / 8), 128>>>(enc, Wmem);

    void* args[] = {
        (void*)&enc, (void*)&lens,
        (void*)&Wih_a, (void*)&Whh_a, (void*)&b_a,
        (void*)&Wq, (void*)&Wconv, (void*)&Wloc, (void*)&v,
        (void*)&Wih_d, (void*)&Whh_d, (void*)&b_d,
        (void*)&Wp, (void*)&bp,
        (void*)&outs, (void*)&aligns
    };
    cudaLaunchCooperativeKernel((void*)persistent_kernel,
                                dim3(NB), dim3(NT), args, SMEM_BYTES, (cudaStream_t)0);
}

// round 17
// speedup vs baseline: 1.0616x; 1.0616x over previous
#include <cuda_runtime.h>
#include <cooperative_groups.h>
#include <cstdint>
#include <cstddef>

namespace cg = cooperative_groups;

#define BB      64
#define TIN     200
#define TOUT    400
#define DENC    512
#define DRNN    1024
#define PRE     256
#define ATT     128
#define KSZ     31
#define NMEL    80
#define GATESZ  4096
#define KSPLIT  8
#define NB      128
#define NT      256
#define WPAD    36
// smem float offsets
#define OFF_XS    (2 * 256 * WPAD)            // 18432
#define OFF_XIN   (OFF_XS + 32 * 68)          // 20608
#define OFF_WLOC  (OFF_XIN + 1536)            // 22144 (persistent)
#define OFF_WC    (OFF_WLOC + 4096)           // 26240 (persistent)
#define OFF_V     (OFF_WC + 1984)             // 28224 (persistent)
#define SMEM_FLOATS (OFF_V + 128)             // 28352
#define SMEM_BYTES  (SMEM_FLOATS * 4)         // 113408

// packed fp32x2 FMA (Blackwell FFMA2) — bit-identical to two scalar FFMAs
#define FMA2(d, a, b) asm("fma.rn.f32x2 %0, %1, %2, %0;" : "+l"(d) : "l"(a), "l"(b))

// ---------------- device scratch ----------------
__device__ float d_xs[(size_t)TOUT * BB * PRE];
__device__ float d_pm[(size_t)BB * TIN * ATT];    // [b][t][a]
__device__ float d_ah[BB * DRNN];
__device__ float d_aca[2][BB * DRNN];             // double-buffered attn cell state
__device__ float d_dh[BB * DRNN];
__device__ float d_dc[BB * DRNN];
__device__ float d_aw[BB * TIN];
__device__ float d_cum[BB * TIN];
__device__ float d_actx[BB * DENC];
__device__ float d_e[BB * TIN];
__device__ float d_gpart_a[(size_t)KSPLIT * GATESZ * BB];   // [s][b][m]
__device__ float d_gpart_d[(size_t)KSPLIT * GATESZ * BB];   // [s][b][m]

// ---------------- fast math ----------------
__device__ __forceinline__ float tanh_fast(float x) {
    float ax = fabsf(x);
    float t  = __expf(-2.0f * ax);
    float r  = __fdividef(1.0f - t, 1.0f + t);
    return copysignf(r, x);
}
__device__ __forceinline__ float sig_fast(float x) {
    return __fdividef(1.0f, 1.0f + __expf(-x));
}

// ---------------- init (runs every replay: determinism) ----------------
__global__ void init_state_kernel() {
    int i = blockIdx.x * 256 + threadIdx.x;
    int n = gridDim.x * 256;
    for (int k = i; k < BB * DRNN; k += n) {
        d_ah[k]=0.f; d_aca[0][k]=0.f; d_aca[1][k]=0.f; d_dh[k]=0.f; d_dc[k]=0.f;
    }
    for (int k = i; k < BB * TIN;  k += n) { d_aw[k]=0.f; d_cum[k]=0.f; }
    for (int k = i; k < BB * DENC; k += n) d_actx[k]=0.f;
}

// ---------------- prenet (all 400 steps, parallel) ----------------
__global__ void prenet_kernel(const float* __restrict__ dec_in,
                              const float* __restrict__ Wp1,
                              const float* __restrict__ Wp2) {
    __shared__ float di_s[32 * NMEL];
    __shared__ float h1_s[32 * PRE];
    int t = blockIdx.x, b0 = blockIdx.y * 32, tid = threadIdx.x;
    for (int i = tid; i < 32 * NMEL; i += 256) {
        int b = i / NMEL, k = i - b * NMEL;
        di_s[i] = (t == 0) ? 0.f : dec_in[((size_t)(t - 1) * BB + (b0 + b)) * NMEL + k];
    }
    __syncthreads();
    {
        const float* wr = Wp1 + tid * NMEL;
        for (int c = 0; c < 2; c++) {
            float acc[16];
            #pragma unroll
            for (int r = 0; r < 16; r++) acc[r] = 0.f;
            for (int k = 0; k < NMEL; k++) {
                float w = wr[k];
                #pragma unroll
                for (int r = 0; r < 16; r++)
                    acc[r] = fmaf(w, di_s[(c * 16 + r) * NMEL + k], acc[r]);
            }
            #pragma unroll
            for (int r = 0; r < 16; r++)
                h1_s[(c * 16 + r) * PRE + tid] = fmaxf(acc[r], 0.f);
        }
    }
    __syncthreads();
    {
        const float* wr = Wp2 + tid * PRE;
        for (int c = 0; c < 2; c++) {
            float acc[16];
            #pragma unroll
            for (int r = 0; r < 16; r++) acc[r] = 0.f;
            for (int k = 0; k < PRE; k++) {
                float w = wr[k];
                #pragma unroll
                for (int r = 0; r < 16; r++)
                    acc[r] = fmaf(w, h1_s[(c * 16 + r) * PRE + k], acc[r]);
            }
            #pragma unroll
            for (int r = 0; r < 16; r++)
                d_xs[((size_t)t * BB + (b0 + c * 16 + r)) * PRE + tid] = fmaxf(acc[r], 0.f);
        }
    }
}

// ---------------- processed memory: pm[b][t][a] ----------------
__global__ void procmem_kernel(const float* __restrict__ enc,
                               const float* __restrict__ Wmem) {
    __shared__ float es[8 * DENC];
    int b = blockIdx.x, t0 = blockIdx.y * 8, tid = threadIdx.x;  // 128 threads
    for (int i = tid; i < 8 * DENC; i += 128)
        es[i] = enc[((size_t)b * TIN + t0) * DENC + i];
    __syncthreads();
    const float* wr = Wmem + tid * DENC;
    float acc[8];
    #pragma unroll
    for (int r = 0; r < 8; r++) acc[r] = 0.f;
    for (int e = 0; e < DENC; e++) {
        float w = wr[e];
        #pragma unroll
        for (int r = 0; r < 8; r++) acc[r] = fmaf(w, es[r * DENC + e], acc[r]);
    }
    #pragma unroll
    for (int r = 0; r < 8; r++)
        d_pm[((size_t)b * TIN + t0 + r) * ATT + tid] = acc[r];
}

// ---------------- GEMM: 8m x 8b tile; W via cp.async double-buffered smem ---
// gpart[split][b][m] = sum_k W[m][k] * x[b][k]; block tile 256m x 64b, chunk 32k
__device__ __forceinline__ void gemm_phase(
    float* smem,
    const float* __restrict__ Wih, int K1,
    const float* __restrict__ Whh,
    const float* __restrict__ x0, int L0,
    const float* __restrict__ x2,
    int kstart, int Kq, int item, float* gpart_base) {
    float* Wsm = smem;                 // 2 x 256 x WPAD
    float* Xs  = smem + OFF_XS;        // 32 x 68
    const int tid = threadIdx.x;
    const int m0 = (item & 15) * 256;
    const int nch = Kq >> 5;
    const int tr = tid >> 3, tb = tid & 7;
    const int L01 = L0 + DENC;
    const int kq4 = (tid & 7) * 4;
    const int jcol = tid & 7;          // 16B piece within a 128B W row

    unsigned long long acc2[8][4];
    #pragma unroll
    for (int m = 0; m < 8; m++)
        #pragma unroll
        for (int p = 0; p < 4; p++) acc2[m][p] = 0ull;

    // stage one 256x32 W chunk into smem buffer via cp.async (8x16B per thread)
    auto stage_w = [&](int kc, int buf) {
        const float* wb; int wstr;
        if (kc < K1) { wb = Wih + kc;        wstr = K1;   }
        else         { wb = Whh + (kc - K1); wstr = 1024; }
        unsigned dbase = (unsigned)__cvta_generic_to_shared(Wsm + buf * 256 * WPAD);
        #pragma unroll
        for (int p = 0; p < 8; p++) {
            int r = (tid >> 3) + 32 * p;
            const float* src = wb + (size_t)(m0 + r) * wstr + jcol * 4;
            unsigned dst = dbase + (unsigned)(r * WPAD + jcol * 4) * 4u;
            asm volatile("cp.async.cg.shared.global [%0], [%1], 16;"
                         :: "r"(dst), "l"(src));
        }
        asm volatile("cp.async.commit_group;");
    };

    float4 xreg[2];
    {   // prologue: W chunk 0 (async) + X chunk 0 (registers)
        stage_w(kstart, 0);
        int kc = kstart;
        const float* xb; int xstr, xcol;
        if (kc < L0)       { xb = x0;     xstr = L0;   xcol = kc; }
        else if (kc < L01) { xb = d_actx; xstr = DENC; xcol = kc - L0; }
        else               { xb = x2;     xstr = 1024; xcol = kc - L01; }
        xreg[0] = *(const float4*)&xb[(size_t)tr * xstr + xcol + kq4];
        xreg[1] = *(const float4*)&xb[(size_t)(tr + 32) * xstr + xcol + kq4];
    }

    for (int c = 0; c < nch; c++) {
        int kc = kstart + c * 32;
        __syncthreads();   // previous chunk's Xs/Wsm reads complete
        {   // stage X (k-major)
            float v0[4] = {xreg[0].x, xreg[0].y, xreg[0].z, xreg[0].w};
            float v1[4] = {xreg[1].x, xreg[1].y, xreg[1].z, xreg[1].w};
            #pragma unroll
            for (int j = 0; j < 4; j++) {
                Xs[(kq4 + j) * 68 + tr]      = v0[j];
                Xs[(kq4 + j) * 68 + tr + 32] = v1[j];
            }
        }
        if (c + 1 < nch) {   // async-prefetch next W chunk + next X chunk
            stage_w(kc + 32, (c + 1) & 1);
            int kn = kc + 32;
            const float* xb; int xstr, xcol;
            if (kn < L0)       { xb = x0;     xstr = L0;   xcol = kn; }
            else if (kn < L01) { xb = d_actx; xstr = DENC; xcol = kn - L0; }
            else               { xb = x2;     xstr = 1024; xcol = kn - L01; }
            xreg[0] = *(const float4*)&xb[(size_t)tr * xstr + xcol + kq4];
            xreg[1] = *(const float4*)&xb[(size_t)(tr + 32) * xstr + xcol + kq4];
            asm volatile("cp.async.wait_group 1;");
        } else {
            asm volatile("cp.async.wait_group 0;");
        }
        __syncthreads();

        const float* wcur = Wsm + (c & 1) * 256 * WPAD + (tr * 8) * WPAD;
        #pragma unroll
        for (int g = 0; g < 8; g++) {
            float4 wr[8];
            #pragma unroll
            for (int i = 0; i < 8; i++)
                wr[i] = *(const float4*)&wcur[i * WPAD + g * 4];
            #pragma unroll
            for (int j = 0; j < 4; j++) {
                int k = g * 4 + j;
                ulonglong2 xa  = *(const ulonglong2*)&Xs[k * 68 + tb * 8];
                ulonglong2 xb2 = *(const ulonglong2*)&Xs[k * 68 + tb * 8 + 4];
                unsigned long long xp0 = xa.x, xp1 = xa.y, xp2 = xb2.x, xp3 = xb2.y;
                #pragma unroll
                for (int m = 0; m < 8; m++) {
                    float wv = ((const float*)&wr[m])[j];
                    unsigned long long w2;
                    unsigned wu = __float_as_uint(wv);
                    asm("mov.b64 %0, {%1, %1};" : "=l"(w2) : "r"(wu));
                    FMA2(acc2[m][0], w2, xp0);
                    FMA2(acc2[m][1], w2, xp1);
                    FMA2(acc2[m][2], w2, xp2);
                    FMA2(acc2[m][3], w2, xp3);
                }
            }
        }
    }

    // write out: gpart[split][b][m]
    float* gp = gpart_base + (size_t)(item >> 4) * (GATESZ * BB);
    #pragma unroll
    for (int p = 0; p < 4; p++) {
        float2 f[8];
        #pragma unroll
        for (int m = 0; m < 8; m++) f[m] = *(float2*)&acc2[m][p];
        int b0 = tb * 8 + 2 * p;
        *(float4*)&gp[(size_t)b0 * GATESZ + m0 + tr * 8] =
            make_float4(f[0].x, f[1].x, f[2].x, f[3].x);
        *(float4*)&gp[(size_t)b0 * GATESZ + m0 + tr * 8 + 4] =
            make_float4(f[4].x, f[5].x, f[6].x, f[7].x);
        *(float4*)&gp[(size_t)(b0 + 1) * GATESZ + m0 + tr * 8] =
            make_float4(f[0].y, f[1].y, f[2].y, f[3].y);
        *(float4*)&gp[(size_t)(b0 + 1) * GATESZ + m0 + tr * 8 + 4] =
            make_float4(f[4].y, f[5].y, f[6].y, f[7].y);
    }
}

// ---------------- per-batch LSTM gates ----------------
__device__ __forceinline__ void gates_batch(const float* __restrict__ bias, int b,
                                            const float* __restrict__ gpart_base,
                                            float* __restrict__ hg,
                                            const float* __restrict__ c_old,
                                            float* __restrict__ c_new,
                                            float* hs, bool write_global) {
    int tid = threadIdx.x;
    #pragma unroll
    for (int r = 0; r < 4; r++) {
        int j = tid + 256 * r;
        float gi = bias[j], gf = bias[j + 1024], gg = bias[j + 2048], go = bias[j + 3072];
        #pragma unroll
        for (int s = 0; s < KSPLIT; s++) {
            const float* gp = gpart_base + (size_t)s * (GATESZ * BB) + (size_t)b * GATESZ;
            gi += gp[j]; gf += gp[j + 1024]; gg += gp[j + 2048]; go += gp[j + 3072];
        }
        float cn = sig_fast(gf) * c_old[b * DRNN + j] + sig_fast(gi) * tanh_fast(gg);
        float hn = sig_fast(go) * tanh_fast(cn);
        if (write_global) { c_new[b * DRNN + j] = cn; hg[b * DRNN + j] = hn; }
        if (hs) hs[j] = hn;
    }
}

// ---------------- dec gates + output projection for step t_prev ----------------
__device__ __forceinline__ void decgates_out(float* xin, const float* __restrict__ b_d,
                                             const float* __restrict__ Wp,
                                             const float* __restrict__ bp,
                                             float* __restrict__ outs, int b, int t_prev) {
    int tid = threadIdx.x;
    gates_batch(b_d, b, d_gpart_d, d_dh, d_dc, d_dc, xin, true);
    for (int i = tid; i < 512; i += 256) xin[1024 + i] = d_actx[b * DENC + i];
    __syncthreads();
    int o = tid >> 1, hf = tid & 1;
    float s0 = 0.f, s1 = 0.f, s2 = 0.f, s3 = 0.f;
    if (o < NMEL) {
        const float4* wr4 = (const float4*)(Wp + (size_t)o * 1536 + hf * 768);
        const float4* xp4 = (const float4*)(xin + hf * 768);
        for (int k = 0; k < 192; k += 4) {
            float4 w0 = wr4[k],     x0 = xp4[k];
            float4 w1 = wr4[k + 1], x1 = xp4[k + 1];
            float4 w2 = wr4[k + 2], x2 = xp4[k + 2];
            float4 w3 = wr4[k + 3], x3 = xp4[k + 3];
            s0 = fmaf(w0.x, x0.x, s0); s0 = fmaf(w0.y, x0.y, s0);
            s0 = fmaf(w0.z, x0.z, s0); s0 = fmaf(w0.w, x0.w, s0);
            s1 = fmaf(w1.x, x1.x, s1); s1 = fmaf(w1.y, x1.y, s1);
            s1 = fmaf(w1.z, x1.z, s1); s1 = fmaf(w1.w, x1.w, s1);
            s2 = fmaf(w2.x, x2.x, s2); s2 = fmaf(w2.y, x2.y, s2);
            s2 = fmaf(w2.z, x2.z, s2); s2 = fmaf(w2.w, x2.w, s2);
            s3 = fmaf(w3.x, x3.x, s3); s3 = fmaf(w3.y, x3.y, s3);
            s3 = fmaf(w3.z, x3.z, s3); s3 = fmaf(w3.w, x3.w, s3);
        }
    }
    float s = (s0 + s1) + (s2 + s3);
    s += __shfl_xor_sync(0xffffffffu, s, 1);
    if (o < NMEL && hf == 0)
        outs[((size_t)b * TOUT + t_prev) * NMEL + o] = s + bp[o];
    __syncthreads();
}

// ---------------- persistent kernel: 4 grid.syncs per step ----------------
// per-step attention scratch (floats, reused region [0, 18432)):
//   ah_s[1024]@0 | aw_s[256]@1024 | cum_s[256]@1280 | pq_s[128]@1536
//   red[32]@1664 | locraw[100*36]@7872
// persistent consts: Wloc@OFF_WLOC | Wconv@OFF_WC | v@OFF_V
__global__ void __launch_bounds__(NT, 1)
persistent_kernel(const float* __restrict__ enc, const int* __restrict__ lens,
                  const float* __restrict__ Wih_a, const float* __restrict__ Whh_a,
                  const float* __restrict__ b_a,
                  const float* __restrict__ Wq, const float* __restrict__ Wconv,
                  const float* __restrict__ Wloc, const float* __restrict__ v,
                  const float* __restrict__ Wih_d, const float* __restrict__ Whh_d,
                  const float* __restrict__ b_d,
                  const float* __restrict__ Wp, const float* __restrict__ bp,
                  float* __restrict__ outs, float* __restrict__ aligns) {
    cg::grid_group grid = cg::this_grid();
    extern __shared__ __align__(16) float pool[];
    const int bid = blockIdx.x, tid = threadIdx.x;
    const int wid = tid >> 5, lane = tid & 31;
    const int bat = bid >> 1, q = bid & 1;   // attention: 2 blocks per batch
    // uneven attn-GEMM K-split: splits 0-3 get 288 k (9 chunks), 4-7 get 160 k
    const int s_a = bid >> 4;
    const int kstart_a = (s_a < 4) ? s_a * 288 : 1152 + (s_a - 4) * 160;
    const int Kq_a = (s_a < 4) ? 288 : 160;

    // one-time: persistent attention constants
    for (int i = tid; i < 4096; i += NT) pool[OFF_WLOC + i] = Wloc[i];
    for (int i = tid; i < 1984; i += NT) pool[OFF_WC + i] = Wconv[i];
    if (tid < 128) pool[OFF_V + tid] = v[tid];
    __syncthreads();
    const float* Wloc_s = pool + OFF_WLOC;
    const float* Wc_s   = pool + OFF_WC;
    const float* v_s    = pool + OFF_V;

    for (int t = 0; t < TOUT; t++) {
        // ======== PA: attn GEMM (uneven); blocks 64..127 also dec-gates+out(t-1)
        gemm_phase(pool, Wih_a, 768, Whh_a,
                   d_xs + (size_t)t * BB * PRE, PRE, d_ah,
                   kstart_a, Kq_a, bid, d_gpart_a);
        if (t > 0 && bid >= 64) {
            __syncthreads();
            decgates_out(pool + OFF_XIN, b_d, Wp, bp, outs, bid - 64, t - 1);
        }
        grid.sync();

        // ======== PC1: gates + pq + conv + energies (2 blocks/batch, 100 pos)
        {
            float* ah_s   = pool;
            float* aw_s   = pool + 1024;
            float* cum_s  = pool + 1280;
            float* pq_s   = pool + 1536;
            float* locraw = pool + 7872;   // [pos_l*36 + f], 100 pos

            for (int i = tid; i < TIN; i += NT) {
                aw_s[i]  = d_aw[bat * TIN + i];
                cum_s[i] = d_cum[bat * TIN + i];
            }
            gates_batch(b_a, bat, d_gpart_a, d_ah,
                        d_aca[t & 1], d_aca[(t + 1) & 1], ah_s, q == 0);
            __syncthreads();

            // pq = Wq @ ah (redundant per block)
            {
                const float4* ah4 = (const float4*)ah_s;
                for (int a = wid * 16; a < wid * 16 + 16; a++) {
                    const float4* wr4 = (const float4*)(Wq + (size_t)a * DRNN);
                    float s = 0.f;
                    for (int k4 = lane; k4 < 256; k4 += 32) {
                        float4 w = wr4[k4]; float4 x = ah4[k4];
                        s = fmaf(w.x, x.x, s); s = fmaf(w.y, x.y, s);
                        s = fmaf(w.z, x.z, s); s = fmaf(w.w, x.w, s);
                    }
                    #pragma unroll
                    for (int o = 16; o > 0; o >>= 1) s += __shfl_xor_sync(0xffffffffu, s, o);
                    if (lane == 0) pq_s[a] = s;
                }
            }
            __syncthreads();

            // conv for this block's 100 positions
            int pos0 = q * 100;
            for (int u = tid; u < 3200; u += NT) {
                int f = u & 31, pos_l = u >> 5;
                int pos = pos0 + pos_l;
                const float* w0 = Wc_s + f * 62;
                float a0 = 0.f;
                #pragma unroll
                for (int kk = 0; kk < KSZ; kk++) {
                    int ip = pos + kk - 15;
                    if (ip >= 0 && ip < TIN)
                        a0 += aw_s[ip] * w0[kk] + cum_s[ip] * w0[31 + kk];
                }
                locraw[pos_l * 36 + f] = a0;
            }
            __syncthreads();

            // energies: FFMA2 pairwise-f dot products, dual a chains
            int ah = tid & 1, pos_l = tid >> 1;
            int len_b = lens[bat];
            int pos = pos0 + pos_l;
            float part = 0.f;
            if (pos_l < 100 && pos < len_b) {
                float4 lr4[8];
                #pragma unroll
                for (int j = 0; j < 8; j++)
                    lr4[j] = *(const float4*)&locraw[pos_l * 36 + j * 4];
                const unsigned long long* lr2 = (const unsigned long long*)lr4;
                const float4* pm4 = (const float4*)(d_pm + ((size_t)bat * TIN + pos) * ATT + ah * 64);
                const float* vv  = v_s + ah * 64;
                const float* pqp = pq_s + ah * 64;
                const float* wl  = Wloc_s + ah * 64 * 32;
                #pragma unroll 4
                for (int i = 0; i < 16; i++) {
                    float4 pmv = pm4[i];
                    #pragma unroll
                    for (int jp = 0; jp < 2; jp++) {
                        int a0 = i * 4 + jp * 2;
                        unsigned long long acc0 = 0ull, acc1 = 0ull;
                        const ulonglong2* w0p = (const ulonglong2*)(wl + a0 * 32);
                        const ulonglong2* w1p = (const ulonglong2*)(wl + a0 * 32 + 32);
                        #pragma unroll
                        for (int p2 = 0; p2 < 8; p2++) {
                            ulonglong2 w0 = w0p[p2];
                            ulonglong2 w1 = w1p[p2];
                            FMA2(acc0, w0.x, lr2[2 * p2]);
                            FMA2(acc0, w0.y, lr2[2 * p2 + 1]);
                            FMA2(acc1, w1.x, lr2[2 * p2]);
                            FMA2(acc1, w1.y, lr2[2 * p2 + 1]);
                        }
                        float2 f0 = *(float2*)&acc0;
                        float2 f1 = *(float2*)&acc1;
                        float lp0 = pqp[a0]     + (f0.x + f0.y);
                        float lp1 = pqp[a0 + 1] + (f1.x + f1.y);
                        float pm0 = ((const float*)&pmv)[jp * 2];
                        float pm1 = ((const float*)&pmv)[jp * 2 + 1];
                        part = fmaf(vv[a0],     tanh_fast(lp0 + pm0), part);
                        part = fmaf(vv[a0 + 1], tanh_fast(lp1 + pm1), part);
                    }
                }
            }
            part += __shfl_xor_sync(0xffffffffu, part, 1);
            if (pos_l < 100 && ah == 0)
                d_e[bat * TIN + pos] = (pos < len_b) ? part : -1.0e8f;
        }
        grid.sync();

        // ======== PC2: shuffle softmax (redundant x2) + context slice
        {
            float* red  = pool + 1664;   // 32 slots
            float* aw_s = pool + 1024;   // 256
            float e = (tid < TIN) ? d_e[bat * TIN + tid] : -3.402823466e38f;
            float m = e;
            #pragma unroll
            for (int o = 16; o > 0; o >>= 1)
                m = fmaxf(m, __shfl_xor_sync(0xffffffffu, m, o));
            if (lane == 0) red[wid] = m;
            __syncthreads();
            if (wid == 0) {
                float mm = (lane < 8) ? red[lane] : -3.402823466e38f;
                #pragma unroll
                for (int o = 4; o > 0; o >>= 1)
                    mm = fmaxf(mm, __shfl_xor_sync(0xffffffffu, mm, o));
                if (lane == 0) red[16] = mm;
            }
            __syncthreads();
            float mx = red[16];
            float p = (tid < TIN) ? __expf(e - mx) : 0.f;
            float su = p;
            #pragma unroll
            for (int o = 16; o > 0; o >>= 1)
                su += __shfl_xor_sync(0xffffffffu, su, o);
            if (lane == 0) red[wid + 8] = su;
            __syncthreads();
            if (wid == 0) {
                float ss = (lane < 8) ? red[lane + 8] : 0.f;
                #pragma unroll
                for (int o = 4; o > 0; o >>= 1)
                    ss += __shfl_xor_sync(0xffffffffu, ss, o);
                if (lane == 0) red[17] = ss;
            }
            __syncthreads();
            float inv = __fdividef(1.0f, red[17]);
            if (tid < TIN) {
                float awn = p * inv;
                aw_s[tid] = awn;
                if (q == 0) {
                    d_aw[bat * TIN + tid]  = awn;
                    d_cum[bat * TIN + tid] = d_cum[bat * TIN + tid] + awn;
                    aligns[((size_t)bat * TOUT + t) * TIN + tid] = awn;
                }
            }
            __syncthreads();
            // context: each thread owns one column; 4 accumulators for MLP
            const float* ep = enc + (size_t)bat * TIN * DENC + q * 256 + tid;
            float a0 = 0.f, a1 = 0.f, a2 = 0.f, a3 = 0.f;
            for (int pz = 0; pz < TIN; pz += 4) {
                a0 = fmaf(aw_s[pz],     ep[(size_t)pz * DENC],       a0);
                a1 = fmaf(aw_s[pz + 1], ep[(size_t)(pz + 1) * DENC], a1);
                a2 = fmaf(aw_s[pz + 2], ep[(size_t)(pz + 2) * DENC], a2);
                a3 = fmaf(aw_s[pz + 3], ep[(size_t)(pz + 3) * DENC], a3);
            }
            d_actx[bat * DENC + q * 256 + tid] = (a0 + a1) + (a2 + a3);
        }
        grid.sync();

        // ======== PD: dec GEMM (even split: 8 x 320) ----
        gemm_phase(pool, Wih_d, 1536, Whh_d, d_ah, 1024, d_dh,
                   (bid >> 4) * 320, 320, bid, d_gpart_d);
        grid.sync();
    }

    // epilogue: final dec gates + out(t = TOUT-1)
    if (bid >= 64) {
        __syncthreads();
        decgates_out(pool + OFF_XIN, b_d, Wp, bp, outs, bid - 64, TOUT - 1);
    }
}

// ---------------- launch ----------------
extern "C" void kernel_launch(void* const* d_in, const int* in_sizes, int n_in,
                              void* d_out, int out_size) {
    const float* enc   = (const float*)d_in[0];
    const float* dec   = (const float*)d_in[1];
    const int*   lens  = (const int*)  d_in[2];
    const float* Wp1   = (const float*)d_in[3];
    const float* Wp2   = (const float*)d_in[4];
    const float* Wih_a = (const float*)d_in[5];
    const float* Whh_a = (const float*)d_in[6];
    const float* b_a   = (const float*)d_in[7];
    const float* Wq    = (const float*)d_in[8];
    const float* Wmem  = (const float*)d_in[9];
    const float* v     = (const float*)d_in[10];
    const float* Wconv = (const float*)d_in[11];
    const float* Wloc  = (const float*)d_in[12];
    const float* Wih_d = (const float*)d_in[13];
    const float* Whh_d = (const float*)d_in[14];
    const float* b_d   = (const float*)d_in[15];
    const float* Wp    = (const float*)d_in[16];
    const float* bp    = (const float*)d_in[17];

    float* outs   = (float*)d_out;
    float* aligns = outs + (size_t)BB * TOUT * NMEL;

    cudaFuncSetAttribute(persistent_kernel,
                         cudaFuncAttributeMaxDynamicSharedMemorySize, SMEM_BYTES);

    init_state_kernel<<<64, 256>>>();
    prenet_kernel<<<dim3(TOUT, 2), 256>>>(dec, Wp1, Wp2);
    procmem_kernel<<<dim3(BB, TIN / 8), 128>>>(enc, Wmem);

    void* args[] = {
        (void*)&enc, (void*)&lens,
        (void*)&Wih_a, (void*)&Whh_a, (void*)&b_a,
        (void*)&Wq, (void*)&Wconv, (void*)&Wloc, (void*)&v,
        (void*)&Wih_d, (void*)&Whh_d, (void*)&b_d,
        (void*)&Wp, (void*)&bp,
        (void*)&outs, (void*)&aligns
    };
    cudaLaunchCooperativeKernel((void*)persistent_kernel,
                                dim3(NB), dim3(NT), args, SMEM_BYTES, (cudaStream_t)0);
}